// round 9
// baseline (speedup 1.0000x reference)
#include <cuda_runtime.h>
#include <cuda_bf16.h>
#include <cstdint>

#define NV 100000
#define NE 800000
#define D  256

// ---------------- device scratch (allocation-free) -------------------------
__device__ __align__(16) float g_aggr[(size_t)NV * D];
__device__ int g_idx_is64;
// W^T split into bf16 hi/lo, 16 chunks of [256 n][64 k]:
// chunks 0-7 = W1 (K=512), 8-11 = W2, 12-15 = W3.
__device__ __align__(16) unsigned short g_Bhi[16][16384];
__device__ __align__(16) unsigned short g_Blo[16][16384];

// ---------------- helpers --------------------------------------------------
__device__ __forceinline__ uint32_t smem_u32(const void* p) {
    uint32_t a;
    asm("{ .reg .u64 t; cvta.to.shared.u64 t, %1; cvt.u32.u64 %0, t; }"
        : "=r"(a) : "l"(p));
    return a;
}
__device__ __forceinline__ void split_bf16(float x, unsigned short& h, unsigned short& l) {
    __nv_bfloat16 hb = __float2bfloat16(x);
    float rem = x - __bfloat162float(hb);
    __nv_bfloat16 lb = __float2bfloat16(rem);
    h = *(unsigned short*)&hb;
    l = *(unsigned short*)&lb;
}
__device__ __forceinline__ void ldm4(unsigned* r, uint32_t addr) {
    asm volatile("ldmatrix.sync.aligned.m8n8.x4.shared.b16 {%0,%1,%2,%3}, [%4];"
                 : "=r"(r[0]), "=r"(r[1]), "=r"(r[2]), "=r"(r[3]) : "r"(addr));
}
__device__ __forceinline__ void mma16816(float* c, const unsigned* a, const unsigned* b) {
    asm volatile("mma.sync.aligned.m16n8k16.row.col.f32.bf16.bf16.f32 "
                 "{%0,%1,%2,%3}, {%4,%5,%6,%7}, {%8,%9}, {%0,%1,%2,%3};"
                 : "+f"(c[0]), "+f"(c[1]), "+f"(c[2]), "+f"(c[3])
                 : "r"(a[0]), "r"(a[1]), "r"(a[2]), "r"(a[3]), "r"(b[0]), "r"(b[1]));
}
__device__ __forceinline__ void cp16(uint32_t d, const void* s) {
    asm volatile("cp.async.cg.shared.global [%0], [%1], 16;"
                 :: "r"(d), "l"(s) : "memory");
}

// ---------------- detect / zero / atomic scatter (proven) ------------------
__global__ void detect_idx_kernel(const int* __restrict__ idx_raw) {
    int is64 = 1;
#pragma unroll 1
    for (int i = 0; i < 64; i++)
        if (idx_raw[2 * i + 1] != 0) { is64 = 0; break; }
    g_idx_is64 = is64;
}

__global__ void zero_aggr_kernel() {
    size_t i = (size_t)blockIdx.x * blockDim.x + threadIdx.x;
    ((float4*)g_aggr)[i] = make_float4(0.f, 0.f, 0.f, 0.f);
}

__global__ void scatter_kernel(const float* __restrict__ efeat,
                               const void* __restrict__ eidx_raw) {
    int e    = blockIdx.x * 8 + (threadIdx.x >> 5);
    int lane = threadIdx.x & 31;
    long long r;
    if (g_idx_is64) r = ((const long long*)eidx_raw)[NE + e];
    else            r = ((const int*)eidx_raw)[NE + e];
    if (r < 0 || r >= NV) return;
    const float4* src = (const float4*)(efeat + (size_t)e * D);
    float* dst = g_aggr + (size_t)r * D;
#pragma unroll
    for (int i = 0; i < 2; i++) {
        int c = lane + i * 32;
        float4 v = src[c];
        asm volatile("red.global.add.v4.f32 [%0], {%1,%2,%3,%4};"
                     :: "l"(dst + c * 4), "f"(v.x), "f"(v.y), "f"(v.z), "f"(v.w)
                     : "memory");
    }
}

// ---------------- weight prep: transpose + hi/lo split ---------------------
__global__ void prep_weights_kernel(const float* __restrict__ W1,
                                    const float* __restrict__ W2,
                                    const float* __restrict__ W3) {
    int chunk = blockIdx.y;                       // 0..15
    int t = blockIdx.x * 256 + threadIdx.x;       // 0..16383
    int n  = t >> 6;                              // 0..255 output col
    int kk = t & 63;                              // 0..63 within chunk
    const float* W; int kbase;
    if (chunk < 8)       { W = W1; kbase = chunk * 64; }
    else if (chunk < 12) { W = W2; kbase = (chunk - 8) * 64; }
    else                 { W = W3; kbase = (chunk - 12) * 64; }
    float w = W[(size_t)(kbase + kk) * 256 + n];
    unsigned short h, l; split_bf16(w, h, l);
    g_Bhi[chunk][n * 64 + kk] = h;
    g_Blo[chunk][n * 64 + kk] = l;
}

// ---------------- mma.sync fused MLP, cp.async pipelined -------------------
// CTA 128 rows x 256 cols, 512 threads = 16 warps (4x4), warp tile 32x64.
// 32 flat half-chunk stages (16 layer1 + 8 layer2 + 8 layer3); the two
// k-halves of the B buffer form a 2-deep cp.async ring.
#define ASTRIDE 528     /* bytes; 132 banks = 4 mod 32 -> conflict-free ldmatrix */
#define BSTRIDE 144     /* bytes;  36 banks = 4 mod 32 */
#define OFS_AHI 0
#define OFS_ALO (128 * ASTRIDE)
#define OFS_BHI (2 * 128 * ASTRIDE)
#define OFS_BLO (OFS_BHI + 256 * BSTRIDE)
#define SMEM_TOTAL (OFS_BLO + 256 * BSTRIDE)   /* 208896 B */

__global__ __launch_bounds__(512, 1)
void mlp_mma_kernel(const float* __restrict__ vfeat,
                    const float* __restrict__ b1,
                    const float* __restrict__ b2,
                    const float* __restrict__ b3,
                    float* __restrict__ out)
{
    extern __shared__ char smem[];
    const uint32_t sb = smem_u32(smem);
    const int tid  = threadIdx.x;
    const int lane = tid & 31;
    const int wid  = tid >> 5;
    const int wr0  = (wid >> 2) * 32;
    const int wc0  = (wid & 3) * 64;
    const int row0 = blockIdx.x * 128;

    const uint32_t aOfs = (uint32_t)(wr0 + (lane & 15)) * ASTRIDE + ((lane >> 4) << 4);
    const uint32_t bOfs = (uint32_t)(wc0 + (lane & 7) + ((lane >> 4) << 3)) * BSTRIDE
                        + (((lane >> 3) & 1) << 4);
    const uint32_t aHi = sb + OFS_AHI + aOfs, aLo = sb + OFS_ALO + aOfs;
    const uint32_t bHi = sb + OFS_BHI + bOfs, bLo = sb + OFS_BLO + bOfs;

    // ---- B stage issuing (each thread: 2 hi + 2 lo 16B copies, 1 group) ----
    auto issueB = [&](int g) {
        if (g >= 32) return;
        int img = (g < 16) ? (g >> 1)
                           : (g < 24) ? (8 + ((g - 16) >> 1))
                                      : (12 + ((g - 24) >> 1));
        int kh = g & 1;
        const char* sh = (const char*)g_Bhi[img];
        const char* sl = (const char*)g_Blo[img];
#pragma unroll
        for (int i = 0; i < 2; i++) {
            int v = i * 512 + tid;              // 0..1023
            int n = v >> 2, q = v & 3;
            uint32_t dofs = (uint32_t)n * BSTRIDE + kh * 64 + q * 16;
            int sofs = n * 128 + kh * 64 + q * 16;
            cp16(sb + OFS_BHI + dofs, sh + sofs);
            cp16(sb + OFS_BLO + dofs, sl + sofs);
        }
        asm volatile("cp.async.commit_group;" ::: "memory");
    };

    // ---- layer-1 A register prefetch state ----
    const int ar  = tid >> 2;                   // staged row 0..127
    const int acb = (tid & 3) * 16;             // col block within chunk
    const bool aok = (row0 + ar) < NV;
    float4 aregs[4];
    auto loadA = [&](int c) {
        const float* src = (c < 4) ? (vfeat + c * 64) : (g_aggr + (c - 4) * 64);
#pragma unroll
        for (int i = 0; i < 4; i++) {
            aregs[i] = make_float4(0.f, 0.f, 0.f, 0.f);
            if (aok) aregs[i] = *(const float4*)(src + (size_t)(row0 + ar) * D + acb + i * 4);
        }
    };
    auto writeA = [&](int c) {
        int slot = c & 3;
        char* ah = smem + OFS_AHI + ar * ASTRIDE + (slot * 64 + acb) * 2;
        char* al = smem + OFS_ALO + ar * ASTRIDE + (slot * 64 + acb) * 2;
#pragma unroll
        for (int i = 0; i < 4; i++) {
            unsigned short h0,l0,h1,l1,h2,l2,h3,l3;
            split_bf16(aregs[i].x, h0, l0); split_bf16(aregs[i].y, h1, l1);
            split_bf16(aregs[i].z, h2, l2); split_bf16(aregs[i].w, h3, l3);
            *(uint2*)(ah + i * 8) = make_uint2((uint32_t)h0 | ((uint32_t)h1 << 16),
                                               (uint32_t)h2 | ((uint32_t)h3 << 16));
            *(uint2*)(al + i * 8) = make_uint2((uint32_t)l0 | ((uint32_t)l1 << 16),
                                               (uint32_t)l2 | ((uint32_t)l3 << 16));
        }
    };

    float acc[2][8][4];
    int g = 0;                                   // current flat stage

    // prologue: first two B stages fly while A chunk 0 loads
    issueB(0); issueB(1);
    loadA(0);

#pragma unroll 1
    for (int layer = 0; layer < 3; layer++) {
#pragma unroll
        for (int i = 0; i < 2; i++)
#pragma unroll
            for (int j = 0; j < 8; j++)
#pragma unroll
                for (int q = 0; q < 4; q++) acc[i][j][q] = 0.f;

        const int nchunks = (layer == 0) ? 8 : 4;
#pragma unroll 1
        for (int c = 0; c < nchunks; c++) {
            if (layer == 0) {
                writeA(c);                       // safe: slot c&3 idle since c-4
                if (c < 7) loadA(c + 1);         // LDGs fly under this chunk's MMAs
            }
#pragma unroll 1
            for (int h = 0; h < 2; h++) {
                if (g == 31) asm volatile("cp.async.wait_group 0;" ::: "memory");
                else         asm volatile("cp.async.wait_group 1;" ::: "memory");
                __syncthreads();                 // stage g + A writes visible

                const int colbase = ((layer == 0) ? (c & 3) : c) * 64;
                const int acol = colbase + h * 32;
#pragma unroll
                for (int k0 = 0; k0 < 32; k0 += 16) {
                    const uint32_t kbA = (uint32_t)(acol + k0) * 2;
                    const uint32_t kbB = (uint32_t)(h * 32 + k0) * 2;
                    unsigned ah4[2][4], bh4[4][4];
                    ldm4(ah4[0], aHi + kbA);
                    ldm4(ah4[1], aHi + 16 * ASTRIDE + kbA);
#pragma unroll
                    for (int blk = 0; blk < 4; blk++)
                        ldm4(bh4[blk], bHi + blk * 16 * BSTRIDE + kbB);
#pragma unroll
                    for (int i = 0; i < 2; i++)
#pragma unroll
                        for (int j = 0; j < 8; j++)
                            mma16816(acc[i][j], ah4[i], &bh4[j >> 1][(j & 1) * 2]);
                    {
                        unsigned bl4[4][4];
#pragma unroll
                        for (int blk = 0; blk < 4; blk++)
                            ldm4(bl4[blk], bLo + blk * 16 * BSTRIDE + kbB);
#pragma unroll
                        for (int i = 0; i < 2; i++)
#pragma unroll
                            for (int j = 0; j < 8; j++)
                                mma16816(acc[i][j], ah4[i], &bl4[j >> 1][(j & 1) * 2]);
                    }
                    {
                        unsigned al4[2][4];
                        ldm4(al4[0], aLo + kbA);
                        ldm4(al4[1], aLo + 16 * ASTRIDE + kbA);
#pragma unroll
                        for (int i = 0; i < 2; i++)
#pragma unroll
                            for (int j = 0; j < 8; j++)
                                mma16816(acc[i][j], al4[i], &bh4[j >> 1][(j & 1) * 2]);
                    }
                }
                __syncthreads();                 // all reads of region (g&1) done
                issueB(g + 2);                   // refill that region
                g++;
            }
        }

        // ---- epilogue (B prefetch for next layer already in flight) ----
        const float* bias = (layer == 0) ? b1 : (layer == 1) ? b2 : b3;
        const int rbase = wr0 + (lane >> 2);
        const int cbase = wc0 + (lane & 3) * 2;
        if (layer < 2) {                         // bias+ReLU -> split -> A smem
#pragma unroll
            for (int i = 0; i < 2; i++)
#pragma unroll
                for (int j = 0; j < 8; j++) {
                    int col = cbase + j * 8;
                    float bb0 = bias[col], bb1 = bias[col + 1];
                    float v0 = fmaxf(acc[i][j][0] + bb0, 0.f);
                    float v1 = fmaxf(acc[i][j][1] + bb1, 0.f);
                    float v2 = fmaxf(acc[i][j][2] + bb0, 0.f);
                    float v3 = fmaxf(acc[i][j][3] + bb1, 0.f);
                    int r0 = rbase + i * 16, r1 = r0 + 8;
                    unsigned short h,l, h2,l2;
                    split_bf16(v0, h, l);  split_bf16(v1, h2, l2);
                    *(uint32_t*)(smem + OFS_AHI + r0 * ASTRIDE + col * 2) =
                        (uint32_t)h | ((uint32_t)h2 << 16);
                    *(uint32_t*)(smem + OFS_ALO + r0 * ASTRIDE + col * 2) =
                        (uint32_t)l | ((uint32_t)l2 << 16);
                    split_bf16(v2, h, l);  split_bf16(v3, h2, l2);
                    *(uint32_t*)(smem + OFS_AHI + r1 * ASTRIDE + col * 2) =
                        (uint32_t)h | ((uint32_t)h2 << 16);
                    *(uint32_t*)(smem + OFS_ALO + r1 * ASTRIDE + col * 2) =
                        (uint32_t)l | ((uint32_t)l2 << 16);
                }
            __syncthreads();                     // activations visible
        } else {                                 // final: bias -> gmem
#pragma unroll
            for (int i = 0; i < 2; i++) {
                int r0 = row0 + rbase + i * 16;
#pragma unroll
                for (int j = 0; j < 8; j++) {
                    int col = cbase + j * 8;
                    float bb0 = bias[col], bb1 = bias[col + 1];
                    if (r0 < NV) {
                        float2 v = make_float2(acc[i][j][0] + bb0, acc[i][j][1] + bb1);
                        *(float2*)(out + (size_t)r0 * D + col) = v;
                    }
                    if (r0 + 8 < NV) {
                        float2 v = make_float2(acc[i][j][2] + bb0, acc[i][j][3] + bb1);
                        *(float2*)(out + (size_t)(r0 + 8) * D + col) = v;
                    }
                }
            }
        }
    }
}

// ---------------------------------------------------------------------------
extern "C" void kernel_launch(void* const* d_in, const int* in_sizes, int n_in,
                              void* d_out, int out_size) {
    const float* vfeat = (const float*)d_in[0];
    const float* efeat = (const float*)d_in[1];
    const void*  eidx  = d_in[2];                 // [2, NE] int64 OR int32
    const float* W1 = (const float*)d_in[3];
    const float* b1 = (const float*)d_in[4];
    const float* W2 = (const float*)d_in[5];
    const float* b2 = (const float*)d_in[6];
    const float* W3 = (const float*)d_in[7];
    const float* b3 = (const float*)d_in[8];
    float* out = (float*)d_out;

    cudaFuncSetAttribute(mlp_mma_kernel,
                         cudaFuncAttributeMaxDynamicSharedMemorySize, SMEM_TOTAL);

    detect_idx_kernel<<<1, 1>>>((const int*)eidx);
    zero_aggr_kernel<<<(NV * D / 4) / 256, 256>>>();
    scatter_kernel<<<NE / 8, 256>>>(efeat, eidx);
    prep_weights_kernel<<<dim3(64, 16), 256>>>(W1, W2, W3);
    mlp_mma_kernel<<<(NV + 127) / 128, 512, SMEM_TOTAL>>>(vfeat, b1, b2, b3, out);
}

// round 11
// speedup vs baseline: 1.4538x; 1.4538x over previous
#include <cuda_runtime.h>
#include <cuda_fp16.h>
#include <cstdint>

#define NV 100000
#define NE 800000
#define D  256

// ---------------- device scratch (allocation-free) -------------------------
__device__ __align__(16) float g_aggr[(size_t)NV * D];
__device__ int g_idx_is64;
// W^T split into fp16 hi + fp16 lo, 16 chunks of [256 n][64 k]:
// chunks 0-7 = W1 (K=512), 8-11 = W2, 12-15 = W3.
__device__ __align__(16) unsigned short g_Bhi[16][16384];
__device__ __align__(16) unsigned short g_Blo[16][16384];
// CSR build scratch
#define SCANB 391                       /* ceil(NV/256) */
__device__ unsigned g_cnt[NV];
__device__ unsigned g_off[NV];
__device__ unsigned g_cur[NV];
__device__ int      g_eid[NE];
__device__ unsigned g_bsum[512];
__device__ unsigned g_boff[512];

// ---------------- helpers --------------------------------------------------
__device__ __forceinline__ uint32_t smem_u32(const void* p) {
    uint32_t a;
    asm("{ .reg .u64 t; cvta.to.shared.u64 t, %1; cvt.u32.u64 %0, t; }"
        : "=r"(a) : "l"(p));
    return a;
}
__device__ __forceinline__ void ldm4(unsigned* r, uint32_t addr) {
    asm volatile("ldmatrix.sync.aligned.m8n8.x4.shared.b16 {%0,%1,%2,%3}, [%4];"
                 : "=r"(r[0]), "=r"(r[1]), "=r"(r[2]), "=r"(r[3]) : "r"(addr));
}
__device__ __forceinline__ void mma16816(float* c, const unsigned* a, const unsigned* b) {
    asm volatile("mma.sync.aligned.m16n8k16.row.col.f32.f16.f16.f32 "
                 "{%0,%1,%2,%3}, {%4,%5,%6,%7}, {%8,%9}, {%0,%1,%2,%3};"
                 : "+f"(c[0]), "+f"(c[1]), "+f"(c[2]), "+f"(c[3])
                 : "r"(a[0]), "r"(a[1]), "r"(a[2]), "r"(a[3]), "r"(b[0]), "r"(b[1]));
}
__device__ __forceinline__ void cp16(uint32_t d, const void* s) {
    asm volatile("cp.async.cg.shared.global [%0], [%1], 16;"
                 :: "r"(d), "l"(s) : "memory");
}
__device__ __forceinline__ uint32_t packh2(float a, float b) {
    __half2 h = __floats2half2_rn(a, b);
    return *(uint32_t*)&h;
}

// ---------------- dtype detect ---------------------------------------------
__global__ void detect_idx_kernel(const int* __restrict__ idx_raw) {
    int is64 = 1;
#pragma unroll 1
    for (int i = 0; i < 64; i++)
        if (idx_raw[2 * i + 1] != 0) { is64 = 0; break; }
    g_idx_is64 = is64;
}
__device__ __forceinline__ int load_recv(const void* eidx_raw, int e) {
    if (g_idx_is64) return (int)((const long long*)eidx_raw)[NE + e];
    return ((const int*)eidx_raw)[NE + e];
}

// ---------------- CSR build: hist -> 3-kernel scan -> fill ------------------
__global__ void zero_cnt_kernel() {
    int i = blockIdx.x * 256 + threadIdx.x;
    if (i < NV) g_cnt[i] = 0;
}
__global__ void hist_kernel(const void* __restrict__ eidx_raw) {
    int e = blockIdx.x * 256 + threadIdx.x;          // 3125 x 256 = NE exact
    int r = load_recv(eidx_raw, e);
    if (r >= 0 && r < NV) atomicAdd(&g_cnt[r], 1u);
}
// per-block inclusive scan of 256 counts -> exclusive offsets + block total
__global__ void scan1_kernel() {
    __shared__ unsigned s[256];
    int t = threadIdx.x, i = blockIdx.x * 256 + t;
    unsigned c = (i < NV) ? g_cnt[i] : 0u;
    s[t] = c;  __syncthreads();
#pragma unroll
    for (int o = 1; o < 256; o <<= 1) {
        unsigned add = (t >= o) ? s[t - o] : 0u;
        __syncthreads(); s[t] += add; __syncthreads();
    }
    if (i < NV) g_off[i] = s[t] - c;                  // exclusive within block
    if (t == 255) g_bsum[blockIdx.x] = s[255];
}
__global__ void scan2_kernel() {                      // 1 block, 512 threads
    __shared__ unsigned s[512];
    int t = threadIdx.x;
    unsigned c = (t < SCANB) ? g_bsum[t] : 0u;
    s[t] = c;  __syncthreads();
#pragma unroll
    for (int o = 1; o < 512; o <<= 1) {
        unsigned add = (t >= o) ? s[t - o] : 0u;
        __syncthreads(); s[t] += add; __syncthreads();
    }
    g_boff[t] = s[t] - c;                             // exclusive block offset
}
__global__ void addback_kernel() {
    int i = blockIdx.x * 256 + threadIdx.x;
    if (i < NV) {
        unsigned o = g_off[i] + g_boff[blockIdx.x];
        g_off[i] = o;  g_cur[i] = o;
    }
}
__global__ void fill_kernel(const void* __restrict__ eidx_raw) {
    int e = blockIdx.x * 256 + threadIdx.x;
    int r = load_recv(eidx_raw, e);
    if (r >= 0 && r < NV) g_eid[atomicAdd(&g_cur[r], 1u)] = e;
}

// ---------------- gather-sum: one warp per vertex, streams edge rows -------
__global__ void gather_kernel(const float* __restrict__ efeat) {
    int v    = blockIdx.x * 8 + (threadIdx.x >> 5);   // 12500 x 8 = NV exact
    int lane = threadIdx.x & 31;
    unsigned start = g_off[v];
    unsigned deg   = g_cnt[v];
    float4 a0 = make_float4(0.f, 0.f, 0.f, 0.f);
    float4 a1 = make_float4(0.f, 0.f, 0.f, 0.f);
    unsigned i = 0;
    for (; i + 2 <= deg; i += 2) {
        int e0 = __ldg(&g_eid[start + i]);
        int e1 = __ldg(&g_eid[start + i + 1]);
        const float4* s0 = (const float4*)(efeat + (size_t)e0 * D);
        const float4* s1 = (const float4*)(efeat + (size_t)e1 * D);
        float4 b0 = __ldg(s0 + lane), b1 = __ldg(s0 + lane + 32);
        float4 c0 = __ldg(s1 + lane), c1 = __ldg(s1 + lane + 32);
        a0.x += b0.x; a0.y += b0.y; a0.z += b0.z; a0.w += b0.w;
        a1.x += b1.x; a1.y += b1.y; a1.z += b1.z; a1.w += b1.w;
        a0.x += c0.x; a0.y += c0.y; a0.z += c0.z; a0.w += c0.w;
        a1.x += c1.x; a1.y += c1.y; a1.z += c1.z; a1.w += c1.w;
    }
    if (i < deg) {
        int e0 = __ldg(&g_eid[start + i]);
        const float4* s0 = (const float4*)(efeat + (size_t)e0 * D);
        float4 b0 = __ldg(s0 + lane), b1 = __ldg(s0 + lane + 32);
        a0.x += b0.x; a0.y += b0.y; a0.z += b0.z; a0.w += b0.w;
        a1.x += b1.x; a1.y += b1.y; a1.z += b1.z; a1.w += b1.w;
    }
    float4* dst = (float4*)(g_aggr + (size_t)v * D);
    dst[lane]      = a0;
    dst[lane + 32] = a1;
}

// ---------------- weight prep: transpose + fp16 hi/lo split ----------------
__global__ void prep_weights_kernel(const float* __restrict__ W1,
                                    const float* __restrict__ W2,
                                    const float* __restrict__ W3) {
    int chunk = blockIdx.y;
    int t = blockIdx.x * 256 + threadIdx.x;
    int n  = t >> 6;
    int kk = t & 63;
    const float* W; int kbase;
    if (chunk < 8)       { W = W1; kbase = chunk * 64; }
    else if (chunk < 12) { W = W2; kbase = (chunk - 8) * 64; }
    else                 { W = W3; kbase = (chunk - 12) * 64; }
    float w = W[(size_t)(kbase + kk) * 256 + n];
    __half wh = __float2half_rn(w);
    __half wl = __float2half_rn(w - __half2float(wh));
    g_Bhi[chunk][n * 64 + kk] = *(unsigned short*)&wh;
    g_Blo[chunk][n * 64 + kk] = *(unsigned short*)&wl;
}

// ---------------- fp16 2-product mma.sync fused MLP ------------------------
// CTA 128 rows x 256 cols, 512 threads = 16 warps (4x4), warp tile 32x64.
// A: single fp16 buffer [128][264]. B: fp16 hi + lo per chunk, cp.async ring
// over the two k-halves (32 flat half-chunk stages).
#define ASTRIDE 528
#define BSTRIDE 144
#define OFS_A   0
#define OFS_BHI (128 * ASTRIDE)
#define OFS_BLO (OFS_BHI + 256 * BSTRIDE)
#define SMEM_TOTAL (OFS_BLO + 256 * BSTRIDE)   /* 141312 B */

__global__ __launch_bounds__(512, 1)
void mlp_mma_kernel(const float* __restrict__ vfeat,
                    const float* __restrict__ b1,
                    const float* __restrict__ b2,
                    const float* __restrict__ b3,
                    float* __restrict__ out)
{
    extern __shared__ char smem[];
    const uint32_t sb = smem_u32(smem);
    const int tid  = threadIdx.x;
    const int lane = tid & 31;
    const int wid  = tid >> 5;
    const int wr0  = (wid >> 2) * 32;
    const int wc0  = (wid & 3) * 64;
    const int row0 = blockIdx.x * 128;

    const uint32_t aOfs = (uint32_t)(wr0 + (lane & 15)) * ASTRIDE + ((lane >> 4) << 4);
    const uint32_t bOfs = (uint32_t)(wc0 + (lane & 7) + ((lane >> 4) << 3)) * BSTRIDE
                        + (((lane >> 3) & 1) << 4);
    const uint32_t aS  = sb + OFS_A   + aOfs;
    const uint32_t bHi = sb + OFS_BHI + bOfs, bLo = sb + OFS_BLO + bOfs;

    auto issueB = [&](int g) {
        if (g >= 32) return;
        int img = (g < 16) ? (g >> 1)
                           : (g < 24) ? (8 + ((g - 16) >> 1))
                                      : (12 + ((g - 24) >> 1));
        int kh = g & 1;
        const char* sh = (const char*)g_Bhi[img];
        const char* sl = (const char*)g_Blo[img];
#pragma unroll
        for (int i = 0; i < 2; i++) {
            int v = i * 512 + tid;              // 0..1023
            int n = v >> 2, q = v & 3;
            uint32_t dofs = (uint32_t)n * BSTRIDE + kh * 64 + q * 16;
            int sofs = n * 128 + kh * 64 + q * 16;
            cp16(sb + OFS_BHI + dofs, sh + sofs);
            cp16(sb + OFS_BLO + dofs, sl + sofs);
        }
        asm volatile("cp.async.commit_group;" ::: "memory");
    };

    // ---- layer-1 A register prefetch ----
    const int ar  = tid >> 2;
    const int acb = (tid & 3) * 16;
    const bool aok = (row0 + ar) < NV;
    float4 aregs[4];
    auto loadA = [&](int c) {
        const float* src = (c < 4) ? (vfeat + c * 64) : (g_aggr + (c - 4) * 64);
#pragma unroll
        for (int i = 0; i < 4; i++) {
            aregs[i] = make_float4(0.f, 0.f, 0.f, 0.f);
            if (aok) aregs[i] = *(const float4*)(src + (size_t)(row0 + ar) * D + acb + i * 4);
        }
    };
    auto writeA = [&](int c) {
        int slot = c & 3;
        char* a = smem + OFS_A + ar * ASTRIDE + (slot * 64 + acb) * 2;
#pragma unroll
        for (int i = 0; i < 4; i++)
            *(uint2*)(a + i * 8) = make_uint2(packh2(aregs[i].x, aregs[i].y),
                                              packh2(aregs[i].z, aregs[i].w));
    };

    float acc[2][8][4];
    int g = 0;

    issueB(0); issueB(1);
    loadA(0);

#pragma unroll 1
    for (int layer = 0; layer < 3; layer++) {
#pragma unroll
        for (int i = 0; i < 2; i++)
#pragma unroll
            for (int j = 0; j < 8; j++)
#pragma unroll
                for (int q = 0; q < 4; q++) acc[i][j][q] = 0.f;

        const int nchunks = (layer == 0) ? 8 : 4;
#pragma unroll 1
        for (int c = 0; c < nchunks; c++) {
            if (layer == 0) {
                writeA(c);
                if (c < 7) loadA(c + 1);
            }
#pragma unroll 1
            for (int h = 0; h < 2; h++) {
                if (g == 31) asm volatile("cp.async.wait_group 0;" ::: "memory");
                else         asm volatile("cp.async.wait_group 1;" ::: "memory");
                __syncthreads();

                const int colbase = ((layer == 0) ? (c & 3) : c) * 64;
                const int acol = colbase + h * 32;
#pragma unroll
                for (int k0 = 0; k0 < 32; k0 += 16) {
                    const uint32_t kbA = (uint32_t)(acol + k0) * 2;
                    const uint32_t kbB = (uint32_t)(h * 32 + k0) * 2;
                    unsigned a4[2][4], bh4[4][4];
                    ldm4(a4[0], aS + kbA);
                    ldm4(a4[1], aS + 16 * ASTRIDE + kbA);
#pragma unroll
                    for (int blk = 0; blk < 4; blk++)
                        ldm4(bh4[blk], bHi + blk * 16 * BSTRIDE + kbB);
#pragma unroll
                    for (int i = 0; i < 2; i++)
#pragma unroll
                        for (int j = 0; j < 8; j++)
                            mma16816(acc[i][j], a4[i], &bh4[j >> 1][(j & 1) * 2]);
                    {
                        unsigned bl4[4][4];
#pragma unroll
                        for (int blk = 0; blk < 4; blk++)
                            ldm4(bl4[blk], bLo + blk * 16 * BSTRIDE + kbB);
#pragma unroll
                        for (int i = 0; i < 2; i++)
#pragma unroll
                            for (int j = 0; j < 8; j++)
                                mma16816(acc[i][j], a4[i], &bl4[j >> 1][(j & 1) * 2]);
                    }
                }
                __syncthreads();
                issueB(g + 2);
                g++;
            }
        }

        // ---- epilogue ----
        const float* bias = (layer == 0) ? b1 : (layer == 1) ? b2 : b3;
        const int rbase = wr0 + (lane >> 2);
        const int cbase = wc0 + (lane & 3) * 2;
        if (layer < 2) {                         // bias+ReLU -> fp16 -> A smem
#pragma unroll
            for (int i = 0; i < 2; i++)
#pragma unroll
                for (int j = 0; j < 8; j++) {
                    int col = cbase + j * 8;
                    float bb0 = bias[col], bb1 = bias[col + 1];
                    float v0 = fmaxf(acc[i][j][0] + bb0, 0.f);
                    float v1 = fmaxf(acc[i][j][1] + bb1, 0.f);
                    float v2 = fmaxf(acc[i][j][2] + bb0, 0.f);
                    float v3 = fmaxf(acc[i][j][3] + bb1, 0.f);
                    int r0 = rbase + i * 16, r1 = r0 + 8;
                    *(uint32_t*)(smem + OFS_A + r0 * ASTRIDE + col * 2) = packh2(v0, v1);
                    *(uint32_t*)(smem + OFS_A + r1 * ASTRIDE + col * 2) = packh2(v2, v3);
                }
            __syncthreads();
        } else {                                 // final: bias -> gmem
#pragma unroll
            for (int i = 0; i < 2; i++) {
                int r0 = row0 + rbase + i * 16;
#pragma unroll
                for (int j = 0; j < 8; j++) {
                    int col = cbase + j * 8;
                    float bb0 = bias[col], bb1 = bias[col + 1];
                    if (r0 < NV) {
                        float2 v = make_float2(acc[i][j][0] + bb0, acc[i][j][1] + bb1);
                        *(float2*)(out + (size_t)r0 * D + col) = v;
                    }
                    if (r0 + 8 < NV) {
                        float2 v = make_float2(acc[i][j][2] + bb0, acc[i][j][3] + bb1);
                        *(float2*)(out + (size_t)(r0 + 8) * D + col) = v;
                    }
                }
            }
        }
    }
}

// ---------------------------------------------------------------------------
extern "C" void kernel_launch(void* const* d_in, const int* in_sizes, int n_in,
                              void* d_out, int out_size) {
    const float* vfeat = (const float*)d_in[0];
    const float* efeat = (const float*)d_in[1];
    const void*  eidx  = d_in[2];                 // [2, NE] int64 OR int32
    const float* W1 = (const float*)d_in[3];
    const float* b1 = (const float*)d_in[4];
    const float* W2 = (const float*)d_in[5];
    const float* b2 = (const float*)d_in[6];
    const float* W3 = (const float*)d_in[7];
    const float* b3 = (const float*)d_in[8];
    float* out = (float*)d_out;

    cudaFuncSetAttribute(mlp_mma_kernel,
                         cudaFuncAttributeMaxDynamicSharedMemorySize, SMEM_TOTAL);

    detect_idx_kernel<<<1, 1>>>((const int*)eidx);
    zero_cnt_kernel<<<SCANB, 256>>>();
    hist_kernel<<<NE / 256, 256>>>(eidx);
    scan1_kernel<<<SCANB, 256>>>();
    scan2_kernel<<<1, 512>>>();
    addback_kernel<<<SCANB, 256>>>();
    fill_kernel<<<NE / 256, 256>>>(eidx);
    gather_kernel<<<NV / 8, 256>>>(efeat);
    prep_weights_kernel<<<dim3(64, 16), 256>>>(W1, W2, W3);
    mlp_mma_kernel<<<(NV + 127) / 128, 512, SMEM_TOTAL>>>(vfeat, b1, b2, b3, out);
}